// round 12
// baseline (speedup 1.0000x reference)
#include <cuda_runtime.h>
#include <cuda_bf16.h>
#include <cstdint>

#define DEV_INLINE __device__ __forceinline__

// ---------------------------------------------------------------------------
// Problem constants
// ---------------------------------------------------------------------------
constexpr int B_ROWS = 4096;
constexpr int N_SVS  = 16384;
constexpr int D_DIM  = 1024;

constexpr int MT     = 128;                 // CTA M tile
constexpr int NT     = 256;                 // CTA N tile
constexpr int KC     = 64;                  // bf16 K elems per chunk (128B rows)
constexpr int NCHUNK = D_DIM / KC;          // 16
constexpr int NTILES = N_SVS / NT;          // 64
constexpr int MBLOCKS = B_ROWS / MT;        // 32
constexpr int NJOBS  = NTILES * MBLOCKS;    // 2048
constexpr int GRID   = 148;                 // persistent: one CTA per SM
constexpr int STAGES = 4;
constexpr int NTHREADS = 288;               // 8 consumer warps + 1 producer warp

constexpr int A_BYTES = MT * 128;           // 16384
constexpr int B_BYTES = NT * 128;           // 32768
constexpr int STAGE_BYTES = A_BYTES + B_BYTES;            // 49152
constexpr int RED_OFF     = 1024 + STAGES * STAGE_BYTES;  // 197632
constexpr int SMEM_TOTAL  = RED_OFF + 4096;               // 201728

constexpr float LOG2E = 1.4426950408889634f;
constexpr float LN2   = 0.6931471805599453f;

// ---------------------------------------------------------------------------
// Device scratch (static, allowed). Tiled + pre-swizzled bf16 copies.
// X layout: chunk c, row m, 128 bytes:  off = (c*4096 + m)*128 + (x ^ ((m&7)<<4))
// S layout: chunk c, row n, 128 bytes:  off = (c*16384 + n)*128 + (x ^ ((n&7)<<4))
// ---------------------------------------------------------------------------
__device__ __align__(1024) unsigned char g_Xt[(size_t)B_ROWS * D_DIM * 2]; // 8 MB
__device__ __align__(1024) unsigned char g_St[(size_t)N_SVS * D_DIM * 2];  // 32 MB
__device__ float g_x2[B_ROWS];
__device__ float g_s2[N_SVS];
__device__ float g_pm[B_ROWS * NTILES];   // per-tile LSE partials, base-2 units
__device__ float g_ps[B_ROWS * NTILES];

// ---------------------------------------------------------------------------
// PTX helpers (baseline ISA only: sm_75/80/90 features, nothing arch-"a")
// ---------------------------------------------------------------------------
DEV_INLINE uint32_t smem_to_u32(const void* p) {
    uint32_t a;
    asm("{ .reg .u64 t; cvta.to.shared.u64 t, %1; cvt.u32.u64 %0, t; }"
        : "=r"(a) : "l"(p));
    return a;
}

#define MBARRIER_INIT(addr, cnt) \
    asm volatile("mbarrier.init.shared.b64 [%0], %1;" \
                 :: "r"((uint32_t)(addr)), "r"((uint32_t)(cnt)) : "memory")

#define MBARRIER_EXPECT_TX(addr, tx) \
    asm volatile("mbarrier.arrive.expect_tx.shared.b64 _, [%0], %1;" \
                 :: "r"((uint32_t)(addr)), "r"((uint32_t)(tx)) : "memory")

#define MBARRIER_ARRIVE(addr) \
    asm volatile("mbarrier.arrive.shared.b64 _, [%0];" \
                 :: "r"((uint32_t)(addr)) : "memory")

#define MBARRIER_WAIT_PARITY(mbar_smem_addr, phase_parity) do { \
    uint32_t _mbar = (uint32_t)(mbar_smem_addr); \
    uint32_t _parity = (uint32_t)(phase_parity); \
    uint32_t _done; \
    asm volatile( \
        "{\n\t.reg .pred p;\n\t" \
        "mbarrier.try_wait.parity.shared.b64 p, [%1], %2;\n\t" \
        "selp.b32 %0, 1, 0, p;\n\t}" \
        : "=r"(_done) : "r"(_mbar), "r"(_parity) : "memory"); \
    if (!_done) { \
        asm volatile( \
            "{\n\t.reg .pred P1;\n\t" \
            "WAIT_LOOP_%=:\n\t" \
            "mbarrier.try_wait.parity.shared.b64 P1, [%0], %1, 0x989680;\n\t" \
            "@P1 bra.uni WAIT_DONE_%=;\n\t" \
            "bra.uni WAIT_LOOP_%=;\n\t" \
            "WAIT_DONE_%=:\n\t}" \
            :: "r"(_mbar), "r"(_parity) : "memory"); \
    } \
} while (0)

#define FENCE_PROXY_ASYNC() asm volatile("fence.proxy.async.shared::cta;" ::: "memory")
#define BAR_CONSUMERS() asm volatile("bar.sync 1, 256;" ::: "memory")

// 1-D bulk async copy global -> shared with mbarrier transaction completion
DEV_INLINE void bulk_g2s(uint32_t dst, const void* src, uint32_t bytes, uint32_t mbar) {
    asm volatile(
        "cp.async.bulk.shared::cluster.global.mbarrier::complete_tx::bytes "
        "[%0], [%1], %2, [%3];"
        :: "r"(dst), "l"(src), "r"(bytes), "r"(mbar) : "memory");
}

DEV_INLINE void ldsm4(uint32_t* r, uint32_t addr) {
    asm volatile("ldmatrix.sync.aligned.m8n8.x4.shared.b16 {%0,%1,%2,%3}, [%4];"
                 : "=r"(r[0]), "=r"(r[1]), "=r"(r[2]), "=r"(r[3]) : "r"(addr));
}

DEV_INLINE void mma_bf16(float* c, const uint32_t* a, uint32_t b0, uint32_t b1) {
    asm volatile(
        "mma.sync.aligned.m16n8k16.row.col.f32.bf16.bf16.f32 "
        "{%0,%1,%2,%3}, {%4,%5,%6,%7}, {%8,%9}, {%0,%1,%2,%3};"
        : "+f"(c[0]), "+f"(c[1]), "+f"(c[2]), "+f"(c[3])
        : "r"(a[0]), "r"(a[1]), "r"(a[2]), "r"(a[3]), "r"(b0), "r"(b1));
}

// ---------------------------------------------------------------------------
// Kernel 1: fp32 -> bf16 convert into tiled/pre-swizzled layout + row sumsq
// One merged launch: blocks [0, B_ROWS) do X, blocks [B_ROWS, B_ROWS+N_SVS) do svs
// ---------------------------------------------------------------------------
__global__ void convert_kernel(const float* __restrict__ X,
                               const float* __restrict__ svs) {
    int b = blockIdx.x;
    const float* src;
    unsigned char* dst;
    float* sq;
    int row, R;
    if (b < B_ROWS) { row = b;          src = X;   dst = g_Xt; sq = g_x2; R = B_ROWS; }
    else            { row = b - B_ROWS; src = svs; dst = g_St; sq = g_s2; R = N_SVS; }

    int t = threadIdx.x;
    float4 v = reinterpret_cast<const float4*>(src + (size_t)row * D_DIM)[t];

    __nv_bfloat16 bb[4];
    bb[0] = __float2bfloat16(v.x);
    bb[1] = __float2bfloat16(v.y);
    bb[2] = __float2bfloat16(v.z);
    bb[3] = __float2bfloat16(v.w);

    int c = t >> 4;                       // chunk = (t*4)/64
    uint32_t xb = (uint32_t)(t & 15) * 8; // byte offset within 128B row
    size_t off = ((size_t)c * R + row) * 128 + (xb ^ (uint32_t)((row & 7) << 4));
    *reinterpret_cast<uint2*>(dst + off) = *reinterpret_cast<uint2*>(bb);

    float ss = v.x * v.x + v.y * v.y + v.z * v.z + v.w * v.w;
#pragma unroll
    for (int o = 16; o > 0; o >>= 1) ss += __shfl_xor_sync(0xffffffffu, ss, o);
    __shared__ float ws[8];
    if ((t & 31) == 0) ws[t >> 5] = ss;
    __syncthreads();
    if (t == 0) {
        float tot = 0.f;
#pragma unroll
        for (int i = 0; i < 8; ++i) tot += ws[i];
        sq[row] = tot;
    }
}

// ---------------------------------------------------------------------------
// Kernel 2: persistent warp-specialized GEMM + fused LSE
// 9 warps: warps 0-7 consumers (2(M) x 4(N) warptile 64x64), warp 8 producer.
// full[s] at sb + s*8 (tx barrier), empty[s] at sb + 32 + s*8 (count 8).
// Fragment double-buffering: ldsm group ks+1 issued under group ks's MMAs,
// including across the chunk boundary (early full-wait + group-0 prefetch).
// ---------------------------------------------------------------------------
__global__ void __launch_bounds__(NTHREADS, 1)
mkde_gemm_kernel(const float* __restrict__ gamma_p) {
    extern __shared__ char smem[];
    uint32_t sb = smem_to_u32(smem);
    int tid = threadIdx.x;
    int lane = tid & 31;
    int wid = tid >> 5;
    int bx = blockIdx.x;

    int nj = (NJOBS - bx + GRID - 1) / GRID;   // 13 or 14 jobs for this CTA
    int totalT = nj * NCHUNK;

    if (tid == 0) {
#pragma unroll
        for (int s = 0; s < STAGES; ++s) {
            MBARRIER_INIT(sb + s * 8, 1);          // full: tx-based
            MBARRIER_INIT(sb + 32 + s * 8, 8);     // empty: 8 consumer warps
        }
        FENCE_PROXY_ASYNC();
    }
    __syncthreads();   // all 288 threads; only CTA-wide barrier in the kernel

    // =======================  PRODUCER (warp 8)  ==========================
    if (wid == 8) {
        if (lane == 0) {
            int stq = 0;
            int eph_arr[STAGES] = {1, 1, 1, 1};  // first waits pass immediately
            for (int t = 0; t < totalT; ++t) {
                MBARRIER_WAIT_PARITY(sb + 32 + stq * 8, eph_arr[stq]);
                int w = t >> 4, c = t & 15;
                int jp = bx + w * GRID;
                int mbp = jp >> 6, ntp = jp & 63;
                uint32_t dst = sb + 1024 + stq * STAGE_BYTES;
                uint32_t fb = sb + stq * 8;
                MBARRIER_EXPECT_TX(fb, (uint32_t)STAGE_BYTES);
                bulk_g2s(dst,
                         g_Xt + ((size_t)c * B_ROWS + (size_t)mbp * MT) * 128,
                         A_BYTES, fb);
                bulk_g2s(dst + A_BYTES,
                         g_St + ((size_t)c * N_SVS + (size_t)ntp * NT) * 128,
                         B_BYTES, fb);
                int used = stq;
                if (++stq == STAGES) stq = 0;
                eph_arr[used] ^= 1;
            }
        }
        return;
    }

    // =======================  CONSUMERS (warps 0-7)  ======================
    int wm = wid >> 2;                 // 0..1 : 64 M rows
    int wn = wid & 3;                  // 0..3 : 64 N cols

    // ldmatrix per-lane address precompute
    int lm = lane >> 3, lr = lane & 7;
    int arow = wm * 64 + ((lm & 1) << 3) + lr;       // + mt*16
    uint32_t aoff = (uint32_t)arow * 128;
    uint32_t asx  = (uint32_t)(arow & 7) << 4;
    uint32_t acol = (uint32_t)(lm >> 1) << 4;        // 0 or 16 bytes
    int brow = wn * 64 + ((lm >> 1) << 3) + lr;      // + p*16
    uint32_t boff = (uint32_t)A_BYTES + (uint32_t)brow * 128;
    uint32_t bsx  = (uint32_t)(brow & 7) << 4;
    uint32_t bcol = (uint32_t)(lm & 1) << 4;

    float gam  = __ldg(gamma_p);
    float gam2 = gam * LOG2E;          // fold log2(e): exp(-g*d) = 2^(-g2*d)
    int lrow = lane >> 2;
    int lcol = (lane & 3) * 2;
    float2* red = reinterpret_cast<float2*>(smem + RED_OFF);  // [4 wn][128 rows]

    int fph[STAGES] = {0, 0, 0, 0};    // consumer full-phase per slot
    int stq = 0;

    // fragment double buffers
    uint32_t fa[2][4][4], fb[2][4][4];

    auto load_group = [&](int buf, uint32_t base, int ks) {
        uint32_t kso = (uint32_t)(ks * 32);
#pragma unroll
        for (int mt = 0; mt < 4; ++mt)
            ldsm4(fa[buf][mt], base + aoff + mt * 2048 + ((kso + acol) ^ asx));
#pragma unroll
        for (int p = 0; p < 4; ++p)
            ldsm4(fb[buf][p], base + boff + p * 2048 + ((kso + bcol) ^ bsx));
    };

    for (int w = 0; w < nj; ++w) {
        int job = bx + w * GRID;
        int mb = job >> 6;
        int ntile = job & 63;
        int nbase = ntile * NT;

        float acc[4][8][4];
#pragma unroll
        for (int mt = 0; mt < 4; ++mt)
#pragma unroll
            for (int nt = 0; nt < 8; ++nt)
#pragma unroll
                for (int q = 0; q < 4; ++q) acc[mt][nt][q] = 0.f;

        // job prologue: wait chunk 0's stage, prefetch its group 0 into buf 0
        MBARRIER_WAIT_PARITY(sb + stq * 8, fph[stq]);
        fph[stq] ^= 1;
        uint32_t base = sb + 1024 + stq * STAGE_BYTES;
        load_group(0, base, 0);

        for (int c = 0; c < NCHUNK; ++c) {
            // group 0 (buf 0): prefetch group 1 -> buf 1, then MMA buf 0
            load_group(1, base, 1);
#pragma unroll
            for (int mt = 0; mt < 4; ++mt)
#pragma unroll
                for (int p = 0; p < 4; ++p) {
                    mma_bf16(acc[mt][p * 2],     fa[0][mt], fb[0][p][0], fb[0][p][1]);
                    mma_bf16(acc[mt][p * 2 + 1], fa[0][mt], fb[0][p][2], fb[0][p][3]);
                }
            // group 1 (buf 1): prefetch group 2 -> buf 0
            load_group(0, base, 2);
#pragma unroll
            for (int mt = 0; mt < 4; ++mt)
#pragma unroll
                for (int p = 0; p < 4; ++p) {
                    mma_bf16(acc[mt][p * 2],     fa[1][mt], fb[1][p][0], fb[1][p][1]);
                    mma_bf16(acc[mt][p * 2 + 1], fa[1][mt], fb[1][p][2], fb[1][p][3]);
                }
            // group 2 (buf 0): prefetch group 3 -> buf 1
            load_group(1, base, 3);
#pragma unroll
            for (int mt = 0; mt < 4; ++mt)
#pragma unroll
                for (int p = 0; p < 4; ++p) {
                    mma_bf16(acc[mt][p * 2],     fa[0][mt], fb[0][p][0], fb[0][p][1]);
                    mma_bf16(acc[mt][p * 2 + 1], fa[0][mt], fb[0][p][2], fb[0][p][3]);
                }
            // group 3 (buf 1): early-wait next chunk + prefetch its group 0 -> buf 0,
            // then MMA buf 1, then release this chunk's stage
            int oldst = stq;
            if (c < NCHUNK - 1) {
                if (++stq == STAGES) stq = 0;
                MBARRIER_WAIT_PARITY(sb + stq * 8, fph[stq]);
                fph[stq] ^= 1;
                base = sb + 1024 + stq * STAGE_BYTES;
                load_group(0, base, 0);
            }
#pragma unroll
            for (int mt = 0; mt < 4; ++mt)
#pragma unroll
                for (int p = 0; p < 4; ++p) {
                    mma_bf16(acc[mt][p * 2],     fa[1][mt], fb[1][p][0], fb[1][p][1]);
                    mma_bf16(acc[mt][p * 2 + 1], fa[1][mt], fb[1][p][2], fb[1][p][3]);
                }
            if (lane == 0) MBARRIER_ARRIVE(sb + 32 + oldst * 8);
        }
        // advance stage for next job (last chunk didn't advance)
        if (++stq == STAGES) stq = 0;

        // ------------- fused epilogue (overlaps producer's bulk loads) ----------
        float x2r[8];
#pragma unroll
        for (int mt = 0; mt < 4; ++mt)
#pragma unroll
            for (int h = 0; h < 2; ++h)
                x2r[mt * 2 + h] = g_x2[mb * MT + wm * 64 + mt * 16 + h * 8 + lrow];

        float s2r[16];
#pragma unroll
        for (int nt = 0; nt < 8; ++nt)
#pragma unroll
            for (int j = 0; j < 2; ++j)
                s2r[nt * 2 + j] = g_s2[nbase + wn * 64 + nt * 8 + lcol + j];

        float mx[8], sm[8];
#pragma unroll
        for (int i = 0; i < 8; ++i) { mx[i] = -3.402823466e38f; sm[i] = 0.f; }

        // pass 1: t = -gam2 * max(dist,0)  (base-2 exponent units)
#pragma unroll
        for (int mt = 0; mt < 4; ++mt)
#pragma unroll
            for (int nt = 0; nt < 8; ++nt)
#pragma unroll
                for (int q = 0; q < 4; ++q) {
                    int h = q >> 1, j = q & 1;
                    float raw = x2r[mt * 2 + h] + s2r[nt * 2 + j]
                                - 2.f * acc[mt][nt][q];
                    float tt = -gam2 * fmaxf(raw, 0.f);
                    acc[mt][nt][q] = tt;
                    mx[mt * 2 + h] = fmaxf(mx[mt * 2 + h], tt);
                }
        // pass 2: sum 2^(t - max)
#pragma unroll
        for (int mt = 0; mt < 4; ++mt)
#pragma unroll
            for (int nt = 0; nt < 8; ++nt)
#pragma unroll
                for (int q = 0; q < 4; ++q) {
                    int h = q >> 1;
                    sm[mt * 2 + h] += exp2f(acc[mt][nt][q] - mx[mt * 2 + h]);
                }

        // reduce across the 4 lanes sharing each row (xor 1, 2)
#pragma unroll
        for (int off = 1; off <= 2; off <<= 1)
#pragma unroll
            for (int i = 0; i < 8; ++i) {
                float mo = __shfl_xor_sync(0xffffffffu, mx[i], off);
                float so = __shfl_xor_sync(0xffffffffu, sm[i], off);
                float M = fmaxf(mx[i], mo);
                sm[i] = sm[i] * exp2f(mx[i] - M) + so * exp2f(mo - M);
                mx[i] = M;
            }

        if ((lane & 3) == 0) {
#pragma unroll
            for (int mt = 0; mt < 4; ++mt)
#pragma unroll
                for (int h = 0; h < 2; ++h) {
                    int row = wm * 64 + mt * 16 + h * 8 + lrow;
                    red[wn * MT + row] = make_float2(mx[mt * 2 + h], sm[mt * 2 + h]);
                }
        }
        BAR_CONSUMERS();

        if (tid < MT) {
            float M = -3.402823466e38f, S = 0.f;
#pragma unroll
            for (int j = 0; j < 4; ++j) {
                float2 v = red[j * MT + tid];
                float Mn = fmaxf(M, v.x);
                S = S * exp2f(M - Mn) + v.y * exp2f(v.x - Mn);
                M = Mn;
            }
            int rg = mb * MT + tid;
            g_pm[rg * NTILES + ntile] = M;
            g_ps[rg * NTILES + ntile] = S;
        }
        BAR_CONSUMERS();
    }
}

// ---------------------------------------------------------------------------
// Kernel 3: combine 64 partials per row -> final output (warp per row)
// Partials are in base-2 exponent units; convert at the end.
// ---------------------------------------------------------------------------
__global__ void combine_kernel(const float* __restrict__ gamma_p,
                               float* __restrict__ out) {
    int gt = blockIdx.x * blockDim.x + threadIdx.x;
    int row = gt >> 5;
    int lane = gt & 31;
    if (row >= B_ROWS) return;

    float m1 = g_pm[row * NTILES + lane];
    float m2 = g_pm[row * NTILES + 32 + lane];
    float s1 = g_ps[row * NTILES + lane];
    float s2 = g_ps[row * NTILES + 32 + lane];
    float M = fmaxf(m1, m2);
    float S = s1 * exp2f(m1 - M) + s2 * exp2f(m2 - M);

#pragma unroll
    for (int off = 16; off > 0; off >>= 1) {
        float mo = __shfl_xor_sync(0xffffffffu, M, off);
        float so = __shfl_xor_sync(0xffffffffu, S, off);
        float Mn = fmaxf(M, mo);
        S = S * exp2f(M - Mn) + so * exp2f(mo - Mn);
        M = Mn;
    }
    if (lane == 0) {
        float gam = gamma_p[0];
        float lse = (M + log2f(S)) * LN2;   // back to base-e
        out[row] = (lse - logf((float)N_SVS)) / (-gam);
    }
}

// ---------------------------------------------------------------------------
// Launch
// ---------------------------------------------------------------------------
extern "C" void kernel_launch(void* const* d_in, const int* in_sizes, int n_in,
                              void* d_out, int out_size) {
    const float* X     = (const float*)d_in[0];
    const float* svs   = (const float*)d_in[1];
    const float* gamma = (const float*)d_in[2];
    float* out = (float*)d_out;
    (void)in_sizes; (void)n_in; (void)out_size;

    cudaFuncSetAttribute(mkde_gemm_kernel,
                         cudaFuncAttributeMaxDynamicSharedMemorySize, SMEM_TOTAL);

    convert_kernel<<<B_ROWS + N_SVS, 256>>>(X, svs);
    mkde_gemm_kernel<<<GRID, NTHREADS, SMEM_TOTAL>>>(gamma);
    combine_kernel<<<(B_ROWS * 32 + 255) / 256, 256>>>(gamma, out);
}

// round 13
// speedup vs baseline: 1.1840x; 1.1840x over previous
#include <cuda_runtime.h>
#include <cuda_bf16.h>
#include <cstdint>

#define DEV_INLINE __device__ __forceinline__

// ---------------------------------------------------------------------------
// Problem constants
// ---------------------------------------------------------------------------
constexpr int B_ROWS = 4096;
constexpr int N_SVS  = 16384;
constexpr int D_DIM  = 1024;

constexpr int MT     = 128;                 // CTA M tile
constexpr int NT     = 256;                 // CTA N tile
constexpr int KC     = 64;                  // bf16 K elems per chunk (128B rows)
constexpr int NCHUNK = D_DIM / KC;          // 16
constexpr int NTILES = N_SVS / NT;          // 64
constexpr int MBLOCKS = B_ROWS / MT;        // 32
constexpr int NJOBS  = NTILES * MBLOCKS;    // 2048
constexpr int GRID   = 148;                 // persistent: one CTA per SM
constexpr int STAGES = 4;
constexpr int NTHREADS = 288;               // 8 consumer warps + 1 producer warp

constexpr int A_BYTES = MT * 128;           // 16384
constexpr int B_BYTES = NT * 128;           // 32768
constexpr int STAGE_BYTES = A_BYTES + B_BYTES;            // 49152
constexpr int RED_OFF     = 1024 + STAGES * STAGE_BYTES;  // 197632
constexpr int SMEM_TOTAL  = RED_OFF + 4096;               // 201728

constexpr float LOG2E = 1.4426950408889634f;
constexpr float LN2   = 0.6931471805599453f;

// ---------------------------------------------------------------------------
// Device scratch (static, allowed). Tiled + pre-swizzled bf16 copies.
// X layout: chunk c, row m, 128 bytes:  off = (c*4096 + m)*128 + (x ^ ((m&7)<<4))
// S layout: chunk c, row n, 128 bytes:  off = (c*16384 + n)*128 + (x ^ ((n&7)<<4))
// ---------------------------------------------------------------------------
__device__ __align__(1024) unsigned char g_Xt[(size_t)B_ROWS * D_DIM * 2]; // 8 MB
__device__ __align__(1024) unsigned char g_St[(size_t)N_SVS * D_DIM * 2];  // 32 MB
__device__ float g_x2[B_ROWS];
__device__ float g_s2[N_SVS];
__device__ float g_pm[B_ROWS * NTILES];   // per-tile LSE partials, base-2 units
__device__ float g_ps[B_ROWS * NTILES];

// ---------------------------------------------------------------------------
// PTX helpers (baseline ISA only: sm_75/80/90 features, nothing arch-"a")
// ---------------------------------------------------------------------------
DEV_INLINE uint32_t smem_to_u32(const void* p) {
    uint32_t a;
    asm("{ .reg .u64 t; cvta.to.shared.u64 t, %1; cvt.u32.u64 %0, t; }"
        : "=r"(a) : "l"(p));
    return a;
}

#define MBARRIER_INIT(addr, cnt) \
    asm volatile("mbarrier.init.shared.b64 [%0], %1;" \
                 :: "r"((uint32_t)(addr)), "r"((uint32_t)(cnt)) : "memory")

#define MBARRIER_EXPECT_TX(addr, tx) \
    asm volatile("mbarrier.arrive.expect_tx.shared.b64 _, [%0], %1;" \
                 :: "r"((uint32_t)(addr)), "r"((uint32_t)(tx)) : "memory")

#define MBARRIER_ARRIVE(addr) \
    asm volatile("mbarrier.arrive.shared.b64 _, [%0];" \
                 :: "r"((uint32_t)(addr)) : "memory")

#define MBARRIER_WAIT_PARITY(mbar_smem_addr, phase_parity) do { \
    uint32_t _mbar = (uint32_t)(mbar_smem_addr); \
    uint32_t _parity = (uint32_t)(phase_parity); \
    uint32_t _done; \
    asm volatile( \
        "{\n\t.reg .pred p;\n\t" \
        "mbarrier.try_wait.parity.shared.b64 p, [%1], %2;\n\t" \
        "selp.b32 %0, 1, 0, p;\n\t}" \
        : "=r"(_done) : "r"(_mbar), "r"(_parity) : "memory"); \
    if (!_done) { \
        asm volatile( \
            "{\n\t.reg .pred P1;\n\t" \
            "WAIT_LOOP_%=:\n\t" \
            "mbarrier.try_wait.parity.shared.b64 P1, [%0], %1, 0x989680;\n\t" \
            "@P1 bra.uni WAIT_DONE_%=;\n\t" \
            "bra.uni WAIT_LOOP_%=;\n\t" \
            "WAIT_DONE_%=:\n\t}" \
            :: "r"(_mbar), "r"(_parity) : "memory"); \
    } \
} while (0)

#define FENCE_PROXY_ASYNC() asm volatile("fence.proxy.async.shared::cta;" ::: "memory")
#define BAR_CONSUMERS() asm volatile("bar.sync 1, 256;" ::: "memory")

// 1-D bulk async copy global -> shared with mbarrier transaction completion
DEV_INLINE void bulk_g2s(uint32_t dst, const void* src, uint32_t bytes, uint32_t mbar) {
    asm volatile(
        "cp.async.bulk.shared::cluster.global.mbarrier::complete_tx::bytes "
        "[%0], [%1], %2, [%3];"
        :: "r"(dst), "l"(src), "r"(bytes), "r"(mbar) : "memory");
}

DEV_INLINE void ldsm4(uint32_t* r, uint32_t addr) {
    asm volatile("ldmatrix.sync.aligned.m8n8.x4.shared.b16 {%0,%1,%2,%3}, [%4];"
                 : "=r"(r[0]), "=r"(r[1]), "=r"(r[2]), "=r"(r[3]) : "r"(addr));
}

DEV_INLINE void mma_bf16(float* c, const uint32_t* a, uint32_t b0, uint32_t b1) {
    asm volatile(
        "mma.sync.aligned.m16n8k16.row.col.f32.bf16.bf16.f32 "
        "{%0,%1,%2,%3}, {%4,%5,%6,%7}, {%8,%9}, {%0,%1,%2,%3};"
        : "+f"(c[0]), "+f"(c[1]), "+f"(c[2]), "+f"(c[3])
        : "r"(a[0]), "r"(a[1]), "r"(a[2]), "r"(a[3]), "r"(b0), "r"(b1));
}

// ---------------------------------------------------------------------------
// Kernel 1: fp32 -> bf16 convert into tiled/pre-swizzled layout + row sumsq
// One merged launch: blocks [0, B_ROWS) do X, blocks [B_ROWS, ...) do svs
// ---------------------------------------------------------------------------
__global__ void convert_kernel(const float* __restrict__ X,
                               const float* __restrict__ svs) {
    int b = blockIdx.x;
    const float* src;
    unsigned char* dst;
    float* sq;
    int row, R;
    if (b < B_ROWS) { row = b;          src = X;   dst = g_Xt; sq = g_x2; R = B_ROWS; }
    else            { row = b - B_ROWS; src = svs; dst = g_St; sq = g_s2; R = N_SVS; }

    int t = threadIdx.x;
    float4 v = reinterpret_cast<const float4*>(src + (size_t)row * D_DIM)[t];

    __nv_bfloat16 bb[4];
    bb[0] = __float2bfloat16(v.x);
    bb[1] = __float2bfloat16(v.y);
    bb[2] = __float2bfloat16(v.z);
    bb[3] = __float2bfloat16(v.w);

    int c = t >> 4;                       // chunk = (t*4)/64
    uint32_t xb = (uint32_t)(t & 15) * 8; // byte offset within 128B row
    size_t off = ((size_t)c * R + row) * 128 + (xb ^ (uint32_t)((row & 7) << 4));
    *reinterpret_cast<uint2*>(dst + off) = *reinterpret_cast<uint2*>(bb);

    float ss = v.x * v.x + v.y * v.y + v.z * v.z + v.w * v.w;
#pragma unroll
    for (int o = 16; o > 0; o >>= 1) ss += __shfl_xor_sync(0xffffffffu, ss, o);
    __shared__ float ws[8];
    if ((t & 31) == 0) ws[t >> 5] = ss;
    __syncthreads();
    if (t == 0) {
        float tot = 0.f;
#pragma unroll
        for (int i = 0; i < 8; ++i) tot += ws[i];
        sq[row] = tot;
    }
}

// ---------------------------------------------------------------------------
// Kernel 2: persistent warp-specialized GEMM + fused LSE  (R11 structure)
// 9 warps: warps 0-7 consumers (2(M) x 4(N) warptile 64x64), warp 8 producer.
// full[s] at sb + s*8 (tx barrier), empty[s] at sb + 32 + s*8 (count 8).
// ---------------------------------------------------------------------------
__global__ void __launch_bounds__(NTHREADS, 1)
mkde_gemm_kernel(const float* __restrict__ gamma_p) {
    extern __shared__ char smem[];
    uint32_t sb = smem_to_u32(smem);
    int tid = threadIdx.x;
    int lane = tid & 31;
    int wid = tid >> 5;
    int bx = blockIdx.x;

    int nj = (NJOBS - bx + GRID - 1) / GRID;   // 13 or 14 jobs for this CTA
    int totalT = nj * NCHUNK;

    if (tid == 0) {
#pragma unroll
        for (int s = 0; s < STAGES; ++s) {
            MBARRIER_INIT(sb + s * 8, 1);          // full: tx-based
            MBARRIER_INIT(sb + 32 + s * 8, 8);     // empty: 8 consumer warps
        }
        FENCE_PROXY_ASYNC();
    }
    __syncthreads();   // all 288 threads; only CTA-wide barrier in the kernel

    // =======================  PRODUCER (warp 8)  ==========================
    if (wid == 8) {
        if (lane == 0) {
            int stq = 0;
            int eph_arr[STAGES] = {1, 1, 1, 1};  // first waits pass immediately
            for (int t = 0; t < totalT; ++t) {
                MBARRIER_WAIT_PARITY(sb + 32 + stq * 8, eph_arr[stq]);
                int w = t >> 4, c = t & 15;
                int jp = bx + w * GRID;
                int mbp = jp >> 6, ntp = jp & 63;
                uint32_t dst = sb + 1024 + stq * STAGE_BYTES;
                uint32_t fb = sb + stq * 8;
                MBARRIER_EXPECT_TX(fb, (uint32_t)STAGE_BYTES);
                bulk_g2s(dst,
                         g_Xt + ((size_t)c * B_ROWS + (size_t)mbp * MT) * 128,
                         A_BYTES, fb);
                bulk_g2s(dst + A_BYTES,
                         g_St + ((size_t)c * N_SVS + (size_t)ntp * NT) * 128,
                         B_BYTES, fb);
                int used = stq;
                if (++stq == STAGES) stq = 0;
                eph_arr[used] ^= 1;
            }
        }
        return;
    }

    // =======================  CONSUMERS (warps 0-7)  ======================
    int wm = wid >> 2;                 // 0..1 : 64 M rows
    int wn = wid & 3;                  // 0..3 : 64 N cols

    // ldmatrix per-lane address precompute
    int lm = lane >> 3, lr = lane & 7;
    int arow = wm * 64 + ((lm & 1) << 3) + lr;       // + mt*16
    uint32_t aoff = (uint32_t)arow * 128;
    uint32_t asx  = (uint32_t)(arow & 7) << 4;
    uint32_t acol = (uint32_t)(lm >> 1) << 4;        // 0 or 16 bytes
    int brow = wn * 64 + ((lm >> 1) << 3) + lr;      // + p*16
    uint32_t boff = (uint32_t)A_BYTES + (uint32_t)brow * 128;
    uint32_t bsx  = (uint32_t)(brow & 7) << 4;
    uint32_t bcol = (uint32_t)(lm & 1) << 4;

    float gam  = __ldg(gamma_p);
    float gam2 = gam * LOG2E;          // fold log2(e): exp(-g*d) = 2^(-g2*d)
    int lrow = lane >> 2;
    int lcol = (lane & 3) * 2;
    float2* red = reinterpret_cast<float2*>(smem + RED_OFF);  // [4 wn][128 rows]

    int fph[STAGES] = {0, 0, 0, 0};    // consumer full-phase per slot
    int stq = 0;

    for (int w = 0; w < nj; ++w) {
        int job = bx + w * GRID;
        int mb = job >> 6;
        int ntile = job & 63;
        int nbase = ntile * NT;

        float acc[4][8][4];
#pragma unroll
        for (int mt = 0; mt < 4; ++mt)
#pragma unroll
            for (int nt = 0; nt < 8; ++nt)
#pragma unroll
                for (int q = 0; q < 4; ++q) acc[mt][nt][q] = 0.f;

        for (int c = 0; c < NCHUNK; ++c) {
            MBARRIER_WAIT_PARITY(sb + stq * 8, fph[stq]);
            fph[stq] ^= 1;

            uint32_t base = sb + 1024 + stq * STAGE_BYTES;
#pragma unroll
            for (int ks = 0; ks < 4; ++ks) {
                uint32_t af[4][4], bf[4][4];
#pragma unroll
                for (int mt = 0; mt < 4; ++mt)
                    ldsm4(af[mt], base + aoff + mt * 2048 +
                                   (((uint32_t)(ks * 32) + acol) ^ asx));
#pragma unroll
                for (int p = 0; p < 4; ++p)
                    ldsm4(bf[p], base + boff + p * 2048 +
                                  (((uint32_t)(ks * 32) + bcol) ^ bsx));
#pragma unroll
                for (int mt = 0; mt < 4; ++mt)
#pragma unroll
                    for (int p = 0; p < 4; ++p) {
                        mma_bf16(acc[mt][p * 2],     af[mt], bf[p][0], bf[p][1]);
                        mma_bf16(acc[mt][p * 2 + 1], af[mt], bf[p][2], bf[p][3]);
                    }
            }
            // this warp is done reading stage stq; free it for the producer
            if (lane == 0) MBARRIER_ARRIVE(sb + 32 + stq * 8);
            if (++stq == STAGES) stq = 0;
        }

        // ------------- fused epilogue (overlaps producer's bulk loads) ----------
        float x2r[8];
#pragma unroll
        for (int mt = 0; mt < 4; ++mt)
#pragma unroll
            for (int h = 0; h < 2; ++h)
                x2r[mt * 2 + h] = g_x2[mb * MT + wm * 64 + mt * 16 + h * 8 + lrow];

        float s2r[16];
#pragma unroll
        for (int nt = 0; nt < 8; ++nt)
#pragma unroll
            for (int j = 0; j < 2; ++j)
                s2r[nt * 2 + j] = g_s2[nbase + wn * 64 + nt * 8 + lcol + j];

        float mx[8], sm[8];
#pragma unroll
        for (int i = 0; i < 8; ++i) { mx[i] = -3.402823466e38f; sm[i] = 0.f; }

        // pass 1: t = -gam2 * max(dist,0)  (base-2 exponent units)
#pragma unroll
        for (int mt = 0; mt < 4; ++mt)
#pragma unroll
            for (int nt = 0; nt < 8; ++nt)
#pragma unroll
                for (int q = 0; q < 4; ++q) {
                    int h = q >> 1, j = q & 1;
                    float raw = x2r[mt * 2 + h] + s2r[nt * 2 + j]
                                - 2.f * acc[mt][nt][q];
                    float tt = -gam2 * fmaxf(raw, 0.f);
                    acc[mt][nt][q] = tt;
                    mx[mt * 2 + h] = fmaxf(mx[mt * 2 + h], tt);
                }
        // pass 2: sum 2^(t - max)
#pragma unroll
        for (int mt = 0; mt < 4; ++mt)
#pragma unroll
            for (int nt = 0; nt < 8; ++nt)
#pragma unroll
                for (int q = 0; q < 4; ++q) {
                    int h = q >> 1;
                    sm[mt * 2 + h] += exp2f(acc[mt][nt][q] - mx[mt * 2 + h]);
                }

        // reduce across the 4 lanes sharing each row (xor 1, 2)
#pragma unroll
        for (int off = 1; off <= 2; off <<= 1)
#pragma unroll
            for (int i = 0; i < 8; ++i) {
                float mo = __shfl_xor_sync(0xffffffffu, mx[i], off);
                float so = __shfl_xor_sync(0xffffffffu, sm[i], off);
                float M = fmaxf(mx[i], mo);
                sm[i] = sm[i] * exp2f(mx[i] - M) + so * exp2f(mo - M);
                mx[i] = M;
            }

        if ((lane & 3) == 0) {
#pragma unroll
            for (int mt = 0; mt < 4; ++mt)
#pragma unroll
                for (int h = 0; h < 2; ++h) {
                    int row = wm * 64 + mt * 16 + h * 8 + lrow;
                    red[wn * MT + row] = make_float2(mx[mt * 2 + h], sm[mt * 2 + h]);
                }
        }
        BAR_CONSUMERS();

        if (tid < MT) {
            float M = -3.402823466e38f, S = 0.f;
#pragma unroll
            for (int j = 0; j < 4; ++j) {
                float2 v = red[j * MT + tid];
                float Mn = fmaxf(M, v.x);
                S = S * exp2f(M - Mn) + v.y * exp2f(v.x - Mn);
                M = Mn;
            }
            int rg = mb * MT + tid;
            g_pm[rg * NTILES + ntile] = M;
            g_ps[rg * NTILES + ntile] = S;
        }
        BAR_CONSUMERS();
    }
}

// ---------------------------------------------------------------------------
// Kernel 3: combine 64 partials per row -> final output (warp per row)
// Partials are in base-2 exponent units; convert at the end.
// ---------------------------------------------------------------------------
__global__ void combine_kernel(const float* __restrict__ gamma_p,
                               float* __restrict__ out) {
    int gt = blockIdx.x * blockDim.x + threadIdx.x;
    int row = gt >> 5;
    int lane = gt & 31;
    if (row >= B_ROWS) return;

    float m1 = g_pm[row * NTILES + lane];
    float m2 = g_pm[row * NTILES + 32 + lane];
    float s1 = g_ps[row * NTILES + lane];
    float s2 = g_ps[row * NTILES + 32 + lane];
    float M = fmaxf(m1, m2);
    float S = s1 * exp2f(m1 - M) + s2 * exp2f(m2 - M);

#pragma unroll
    for (int off = 16; off > 0; off >>= 1) {
        float mo = __shfl_xor_sync(0xffffffffu, M, off);
        float so = __shfl_xor_sync(0xffffffffu, S, off);
        float Mn = fmaxf(M, mo);
        S = S * exp2f(M - Mn) + so * exp2f(mo - Mn);
        M = Mn;
    }
    if (lane == 0) {
        float gam = gamma_p[0];
        float lse = (M + log2f(S)) * LN2;   // back to base-e
        out[row] = (lse - logf((float)N_SVS)) / (-gam);
    }
}

// ---------------------------------------------------------------------------
// Launch
// ---------------------------------------------------------------------------
extern "C" void kernel_launch(void* const* d_in, const int* in_sizes, int n_in,
                              void* d_out, int out_size) {
    const float* X     = (const float*)d_in[0];
    const float* svs   = (const float*)d_in[1];
    const float* gamma = (const float*)d_in[2];
    float* out = (float*)d_out;
    (void)in_sizes; (void)n_in; (void)out_size;

    cudaFuncSetAttribute(mkde_gemm_kernel,
                         cudaFuncAttributeMaxDynamicSharedMemorySize, SMEM_TOTAL);

    convert_kernel<<<B_ROWS + N_SVS, 256>>>(X, svs);
    mkde_gemm_kernel<<<GRID, NTHREADS, SMEM_TOTAL>>>(gamma);
    combine_kernel<<<(B_ROWS * 32 + 255) / 256, 256>>>(gamma, out);
}